// round 15
// baseline (speedup 1.0000x reference)
#include <cuda_runtime.h>
#include <cuda_fp16.h>
#include <math.h>

// ---------------- problem constants ----------------
#define NN    20000
#define EE    400000
#define ET    (EE + NN)
#define GG    200
#define C1    64
#define C2    32

// ---------------- persistent scratch ----------------
__device__ __align__(16) __half   g_xl[NN * 256];   // fp16 message table
__device__ __align__(16) float    g_xr[NN * 256];   // fp32 query table
__device__ __align__(16) float    g_h [NN * 64];    // inter-layer activations
__device__ __align__(16) __half2  g_w2h[32 * 256];  // packed layer-2 weights
__device__ __align__(16) int      g_deg[NN];
__device__ __align__(16) int      g_pos[EE];
__device__ __align__(16) int      g_rowptr[NN + 4];
__device__ int                    g_csr[ET];

// ---------------- kernel 1: count (+slot record) fused with w2 pack ----
#define CNT_BLK 391                       // ceil(EE/4/256)
__global__ void countprep_kernel(const int* __restrict__ ei,
                                 const float* __restrict__ Wl2,
                                 const float* __restrict__ Wr2) {
    if (blockIdx.x < CNT_BLK) {
        int i = blockIdx.x * blockDim.x + threadIdx.x;
        if (i >= EE / 4) return;
        int4 d = reinterpret_cast<const int4*>(ei + EE)[i];
        int4 p;
        p.x = atomicAdd(&g_deg[d.x], 1);
        p.y = atomicAdd(&g_deg[d.y], 1);
        p.z = atomicAdd(&g_deg[d.z], 1);
        p.w = atomicAdd(&g_deg[d.w], 1);
        reinterpret_cast<int4*>(g_pos)[i] = p;
    } else {
        int i = (blockIdx.x - CNT_BLK) * blockDim.x + threadIdx.x;
        if (i >= 32 * 256) return;
        int kp = i >> 8, c = i & 255;
        float a, b;
        if (c < 128) { a = Wl2[(2 * kp) * 128 + c];       b = Wl2[(2 * kp + 1) * 128 + c]; }
        else         { a = Wr2[(2 * kp) * 128 + c - 128]; b = Wr2[(2 * kp + 1) * 128 + c - 128]; }
        g_w2h[i] = __floats2half2_rn(a, b);
    }
}

// ---------------- kernel 2: scan ----------------
__global__ void scan_kernel() {
    __shared__ int sbuf[1024];
    int t = threadIdx.x;
    int4 v[5];
    int s = 0;
    const int4* d4 = reinterpret_cast<const int4*>(g_deg);
    if (t < 1000) {
#pragma unroll
        for (int i = 0; i < 5; i++) {
            v[i] = d4[t * 5 + i];
            s += v[i].x + v[i].y + v[i].z + v[i].w + 4;
        }
    }
    sbuf[t] = s;
    __syncthreads();
#pragma unroll
    for (int off = 1; off < 1024; off <<= 1) {
        int vv = (t >= off) ? sbuf[t - off] : 0;
        __syncthreads();
        sbuf[t] += vv;
        __syncthreads();
    }
    if (t < 1000) {
        int run = sbuf[t] - s;
        int4* rp4 = reinterpret_cast<int4*>(g_rowptr);
#pragma unroll
        for (int i = 0; i < 5; i++) {
            int4 o;
            o.x = run; run += v[i].x + 1;
            o.y = run; run += v[i].y + 1;
            o.z = run; run += v[i].z + 1;
            o.w = run; run += v[i].w + 1;
            rp4[t * 5 + i] = o;
        }
    }
    if (t == 1023) g_rowptr[NN] = sbuf[1023];
}

// ---------------- kernel 3: fill (1 edge/thread) fused with lin1 -------
#define FILL_BLK 1641                     // ceil(ET/256)
__global__ void __launch_bounds__(256, 6)
filllin1_kernel(const int* __restrict__ ei,
                const float* __restrict__ x,
                const float* __restrict__ Wl, const float* __restrict__ bl,
                const float* __restrict__ Wr, const float* __restrict__ br,
                __half* __restrict__ xl, float* __restrict__ xr) {
    if (blockIdx.x < FILL_BLK) {
        int i = blockIdx.x * blockDim.x + threadIdx.x;
        if (i >= ET) return;
        if (i < EE) {
            int src = ei[i];
            int dst = ei[EE + i];
            int pos = g_pos[i];
            g_csr[g_rowptr[dst] + pos] = src;
        } else {
            int n = i - EE;                // self loop -> last slot of row
            g_csr[g_rowptr[n] + g_deg[n]] = n;
        }
        return;
    }
    // ---- lin1: 8 rows per block, 256 threads ----
    __shared__ float xs[8 * 8];
    int n0 = (blockIdx.x - FILL_BLK) * 8;
    int tid = threadIdx.x;
    if (tid < 16)
        reinterpret_cast<float4*>(xs)[tid] =
            reinterpret_cast<const float4*>(x + n0 * 8)[tid];
    __syncthreads();

    int co = tid & 127;
    int r0 = (tid >> 7) * 4;
    int col = co * 4;
    bool left = (col < 256);
    const float* W    = left ? (Wl + col) : (Wr + col - 256);
    const float* bptr = left ? (bl + col) : (br + col - 256);
    float4 bv = *reinterpret_cast<const float4*>(bptr);
    float4 acc[4];
#pragma unroll
    for (int i = 0; i < 4; i++) acc[i] = bv;

#pragma unroll
    for (int k = 0; k < 8; k++) {
        float4 w = *reinterpret_cast<const float4*>(W + k * 256);
#pragma unroll
        for (int i = 0; i < 4; i++) {
            float xv = xs[(r0 + i) * 8 + k];
            acc[i].x += xv * w.x;
            acc[i].y += xv * w.y;
            acc[i].z += xv * w.z;
            acc[i].w += xv * w.w;
        }
    }
    if (left) {
#pragma unroll
        for (int i = 0; i < 4; i++) {
            __half2* p = reinterpret_cast<__half2*>(xl + (n0 + r0 + i) * 256 + col);
            p[0] = __floats2half2_rn(acc[i].x, acc[i].y);
            p[1] = __floats2half2_rn(acc[i].z, acc[i].w);
        }
    } else {
        int oc = col - 256;
#pragma unroll
        for (int i = 0; i < 4; i++)
            *reinterpret_cast<float4*>(xr + (n0 + r0 + i) * 256 + oc) = acc[i];
    }
}

// ---------------- kernel 4: GATv2 (2 warps per node, split edge list) --
template <int C, bool FINAL>
__global__ void gat_kernel(const __half* __restrict__ xl, const float* __restrict__ xr,
                           const float* __restrict__ att, const float* __restrict__ bias,
                           const float* __restrict__ lng, const float* __restrict__ lnb,
                           const int* __restrict__ batch, float* __restrict__ outp) {
    constexpr int D   = 4 * C;
    constexpr int VPL = C / 8;
    constexpr int H2  = VPL / 2;
    constexpr int F4  = VPL / 4;          // float4s per lane (2 for C=64, 1 for C=32)
    __shared__ float4 accsh[32 * F4];
    __shared__ float  ssh[32];            // per-lane (== per-head-group) partial s

    int gw = blockIdx.x;
    int w    = threadIdx.x >> 5;
    int lane = threadIdx.x & 31;
    int h  = lane >> 3;
    int cl = lane & 7;

    __half2 a2[H2], q2[H2];
    const float* attp = att + h * C + cl * VPL;
    const float* qp   = xr + gw * D + lane * VPL;
#pragma unroll
    for (int i = 0; i < H2; i++) {
        a2[i] = __floats2half2_rn(attp[2 * i] * 1.44269504f,
                                  attp[2 * i + 1] * 1.44269504f);
        q2[i] = __floats2half2_rn(qp[2 * i], qp[2 * i + 1]);
    }
    float acc[VPL];
#pragma unroll
    for (int i = 0; i < VPL; i++) acc[i] = 0.f;
    float s = 0.f;

    const __half2 c02 = __floats2half2_rn(0.2f, 0.2f);
    const __half* rowp = xl + lane * VPL;

    auto loadv = [&](__half2* hv, int src) {
        if (C == 64)
            *reinterpret_cast<uint4*>(hv) = *reinterpret_cast<const uint4*>(rowp + src * D);
        else
            *reinterpret_cast<uint2*>(hv) = *reinterpret_cast<const uint2*>(rowp + src * D);
    };
    auto score = [&](__half2* hv) -> __half2 {
        __half2 p2 = __floats2half2_rn(0.f, 0.f);
#pragma unroll
        for (int i = 0; i < H2; i++) {
            __half2 v  = __hadd2(hv[i], q2[i]);
            __half2 lr = __hmax2(v, __hmul2(v, c02));
            p2 = __hfma2(a2[i], lr, p2);
        }
        return p2;
    };

    // split this node's edge list between the two warps
    int kb0 = g_rowptr[gw], ke0 = g_rowptr[gw + 1];
    int half = (ke0 - kb0 + 1) >> 1;      // warp 0 takes the ceil half
    int kb = w ? kb0 + half : kb0;
    int ke = w ? ke0        : kb0 + half;

    int k = kb;
    int i0, i1, i2, i3;
    if (k + 4 <= ke) {
        i0 = g_csr[k]; i1 = g_csr[k + 1]; i2 = g_csr[k + 2]; i3 = g_csr[k + 3];
    }
    while (k + 4 <= ke) {
        __half2 hv0[H2], hv1[H2], hv2[H2], hv3[H2];
        loadv(hv0, i0); loadv(hv1, i1); loadv(hv2, i2); loadv(hv3, i3);
        k += 4;
        if (k + 4 <= ke) {   // prefetch next group's indices
            i0 = g_csr[k]; i1 = g_csr[k + 1]; i2 = g_csr[k + 2]; i3 = g_csr[k + 3];
        }
        __half2 p0 = score(hv0), p1 = score(hv1), p2 = score(hv2), p3 = score(hv3);
        __half2 r01 = __hadd2(__lows2half2(p0, p1), __highs2half2(p0, p1));
        __half2 r23 = __hadd2(__lows2half2(p2, p3), __highs2half2(p2, p3));
#pragma unroll
        for (int off = 1; off < 8; off <<= 1) {
            unsigned u01 = __shfl_xor_sync(0xffffffffu,
                           *reinterpret_cast<unsigned*>(&r01), off);
            unsigned u23 = __shfl_xor_sync(0xffffffffu,
                           *reinterpret_cast<unsigned*>(&r23), off);
            r01 = __hadd2(r01, *reinterpret_cast<__half2*>(&u01));
            r23 = __hadd2(r23, *reinterpret_cast<__half2*>(&u23));
        }
        float2 f01 = __half22float2(r01);
        float2 f23 = __half22float2(r23);
        float al0 = exp2f(f01.x);
        float al1 = exp2f(f01.y);
        float al2 = exp2f(f23.x);
        float al3 = exp2f(f23.y);
        s += (al0 + al1) + (al2 + al3);
        __half2 al0h = __float2half2_rn(al0);
        __half2 al1h = __float2half2_rn(al1);
        __half2 al2h = __float2half2_rn(al2);
        __half2 al3h = __float2half2_rn(al3);
#pragma unroll
        for (int i = 0; i < H2; i++) {
            __half2 t = __hmul2(al0h, hv0[i]);
            t = __hfma2(al1h, hv1[i], t);
            __half2 u = __hmul2(al2h, hv2[i]);
            u = __hfma2(al3h, hv3[i], u);
            float2 ft = __half22float2(t);
            float2 fu = __half22float2(u);
            acc[2 * i]     += ft.x + fu.x;
            acc[2 * i + 1] += ft.y + fu.y;
        }
    }
    for (; k < ke; k++) {
        __half2 hv[H2];
        loadv(hv, g_csr[k]);
        __half2 p2 = score(hv);
#pragma unroll
        for (int off = 1; off < 8; off <<= 1) {
            unsigned pu = __shfl_xor_sync(0xffffffffu,
                          *reinterpret_cast<unsigned*>(&p2), off);
            p2 = __hadd2(p2, *reinterpret_cast<__half2*>(&pu));
        }
        float2 pf = __half22float2(p2);
        float al = exp2f(pf.x + pf.y);
        s += al;
#pragma unroll
        for (int i = 0; i < H2; i++) {
            float2 f = __half22float2(hv[i]);
            acc[2 * i]     += al * f.x;
            acc[2 * i + 1] += al * f.y;
        }
    }

    // warp 1 publishes its per-lane partials (s, acc); warp 0 combines
    if (w == 1) {
        ssh[lane] = s;
#pragma unroll
        for (int j = 0; j < F4; j++)
            accsh[lane * F4 + j] = make_float4(acc[4 * j], acc[4 * j + 1],
                                               acc[4 * j + 2], acc[4 * j + 3]);
    }
    __syncthreads();
    if (w == 1) return;

    s += ssh[lane];
#pragma unroll
    for (int j = 0; j < F4; j++) {
        float4 v = accsh[lane * F4 + j];
        acc[4 * j]     += v.x;
        acc[4 * j + 1] += v.y;
        acc[4 * j + 2] += v.z;
        acc[4 * j + 3] += v.w;
    }

    float inv = 1.f / s;
#pragma unroll
    for (int i = 0; i < VPL; i++) acc[i] *= inv;
#pragma unroll
    for (int i = 0; i < VPL; i++) {
        acc[i] += __shfl_xor_sync(0xffffffffu, acc[i], 8);
        acc[i] += __shfl_xor_sync(0xffffffffu, acc[i], 16);
    }
    float u[VPL];
    const float* bp = bias + cl * VPL;
    float tot = 0.f;
#pragma unroll
    for (int i = 0; i < VPL; i++) { u[i] = acc[i] * 0.25f + bp[i]; tot += u[i]; }
#pragma unroll
    for (int off = 16; off >= 1; off >>= 1)
        tot += __shfl_xor_sync(0xffffffffu, tot, off);
    float mean = tot * (1.f / (4.f * C));
    float d[VPL], var = 0.f;
#pragma unroll
    for (int i = 0; i < VPL; i++) { d[i] = u[i] - mean; var += d[i] * d[i]; }
#pragma unroll
    for (int off = 16; off >= 1; off >>= 1)
        var += __shfl_xor_sync(0xffffffffu, var, off);
    float rstd = rsqrtf(var * (1.f / (4.f * C)) + 1e-5f);

    const float* gp = lng + cl * VPL;
    const float* b2 = lnb + cl * VPL;
    float y[VPL];
#pragma unroll
    for (int i = 0; i < VPL; i++)
        y[i] = fmaxf(d[i] * rstd * gp[i] + b2[i], 0.f);

    if (lane < 8) {
        if (FINAL) {
            int bg = batch[gw];
#pragma unroll
            for (int i = 0; i < VPL; i++)
                atomicAdd(&outp[bg * C + cl * VPL + i], y[i]);
        } else {
            float* op = outp + gw * C + cl * VPL;
            *reinterpret_cast<float4*>(op) = make_float4(y[0], y[1], y[2], y[3]);
            if (VPL == 8)
                *reinterpret_cast<float4*>(op + 4) = make_float4(y[4], y[5], y[6], y[7]);
        }
    }
}

// ---------------- kernel 5: layer-2 linear (half2 split-K) ----------------
__global__ void __launch_bounds__(512, 2)
lin2_kernel(const float* __restrict__ xin,
            const float* __restrict__ bl, const float* __restrict__ br,
            __half* __restrict__ xl, float* __restrict__ xr) {
    __shared__ __half2 xs2[32 * 32];
    int n0 = blockIdx.x * 32;
    int tid = threadIdx.x;
    for (int idx = tid; idx < 32 * 32; idx += 512) {
        int row = idx >> 5, kp = idx & 31;
        float2 v = *reinterpret_cast<const float2*>(xin + (n0 + row) * 64 + 2 * kp);
        xs2[idx] = __floats2half2_rn(v.x, v.y);
    }
    __syncthreads();

    int co = tid & 63;
    int r0 = (tid >> 6) * 4;
    int col = co * 4;
    bool left = (col < 128);
    const float* bptr = left ? (bl + col) : (br + col - 128);
    float4 bv = *reinterpret_cast<const float4*>(bptr);
    float4 accf[4];
#pragma unroll
    for (int i = 0; i < 4; i++) accf[i] = bv;

    const __half2* wp = g_w2h + co * 4;
#pragma unroll
    for (int ch = 0; ch < 2; ch++) {
        __half2 ah[4][4];
#pragma unroll
        for (int r = 0; r < 4; r++)
#pragma unroll
            for (int c = 0; c < 4; c++) ah[r][c] = __floats2half2_rn(0.f, 0.f);
#pragma unroll
        for (int kp = 0; kp < 16; kp++) {
            int kk = ch * 16 + kp;
            uint4 wv = *reinterpret_cast<const uint4*>(wp + kk * 256);
            __half2 w0 = *reinterpret_cast<__half2*>(&wv.x);
            __half2 w1 = *reinterpret_cast<__half2*>(&wv.y);
            __half2 w2 = *reinterpret_cast<__half2*>(&wv.z);
            __half2 w3 = *reinterpret_cast<__half2*>(&wv.w);
#pragma unroll
            for (int r = 0; r < 4; r++) {
                __half2 xp = xs2[(r0 + r) * 32 + kk];
                ah[r][0] = __hfma2(xp, w0, ah[r][0]);
                ah[r][1] = __hfma2(xp, w1, ah[r][1]);
                ah[r][2] = __hfma2(xp, w2, ah[r][2]);
                ah[r][3] = __hfma2(xp, w3, ah[r][3]);
            }
        }
#pragma unroll
        for (int r = 0; r < 4; r++) {
            float2 f;
            f = __half22float2(ah[r][0]); accf[r].x += f.x + f.y;
            f = __half22float2(ah[r][1]); accf[r].y += f.x + f.y;
            f = __half22float2(ah[r][2]); accf[r].z += f.x + f.y;
            f = __half22float2(ah[r][3]); accf[r].w += f.x + f.y;
        }
    }

    if (left) {
#pragma unroll
        for (int i = 0; i < 4; i++) {
            __half2* p = reinterpret_cast<__half2*>(xl + (n0 + r0 + i) * 128 + col);
            p[0] = __floats2half2_rn(accf[i].x, accf[i].y);
            p[1] = __floats2half2_rn(accf[i].z, accf[i].w);
        }
    } else {
        int oc = col - 128;
#pragma unroll
        for (int i = 0; i < 4; i++)
            *reinterpret_cast<float4*>(xr + (n0 + r0 + i) * 128 + oc) = accf[i];
    }
}

// ---------------- kernel 6: divide pooled sums ----------------
__global__ void div_kernel(const int* __restrict__ batch, float* __restrict__ out) {
    int t = threadIdx.x;
    if (t >= GG) return;
    int lo0 = 0, hi0 = NN;
    while (lo0 < hi0) { int mid = (lo0 + hi0) >> 1; if (batch[mid] < t) lo0 = mid + 1; else hi0 = mid; }
    int lo1 = lo0, hi1 = NN;
    while (lo1 < hi1) { int mid = (lo1 + hi1) >> 1; if (batch[mid] < t + 1) lo1 = mid + 1; else hi1 = mid; }
    float invc = 1.f / fmaxf((float)(lo1 - lo0), 1.f);
    float4* o4 = reinterpret_cast<float4*>(out + t * C2);
#pragma unroll
    for (int i = 0; i < C2 / 4; i++) {
        float4 v = o4[i];
        v.x *= invc; v.y *= invc; v.z *= invc; v.w *= invc;
        o4[i] = v;
    }
}

// ---------------- launch ----------------
extern "C" void kernel_launch(void* const* d_in, const int* in_sizes, int n_in,
                              void* d_out, int out_size) {
    const float* x     = (const float*)d_in[0];
    const int*   ei    = (const int*)  d_in[1];
    const int*   batch = (const int*)  d_in[2];
    const float* Wl1   = (const float*)d_in[3];
    const float* bl1   = (const float*)d_in[4];
    const float* Wr1   = (const float*)d_in[5];
    const float* br1   = (const float*)d_in[6];
    const float* att1  = (const float*)d_in[7];
    const float* b1    = (const float*)d_in[8];
    const float* ln1g  = (const float*)d_in[9];
    const float* ln1b  = (const float*)d_in[10];
    const float* Wl2   = (const float*)d_in[11];
    const float* bl2   = (const float*)d_in[12];
    const float* Wr2   = (const float*)d_in[13];
    const float* br2   = (const float*)d_in[14];
    const float* att2  = (const float*)d_in[15];
    const float* b2    = (const float*)d_in[16];
    const float* ln2g  = (const float*)d_in[17];
    const float* ln2b  = (const float*)d_in[18];
    float* out = (float*)d_out;

    __half* xl; float *xr, *h; int* degp;
    cudaGetSymbolAddress((void**)&xl,   g_xl);
    cudaGetSymbolAddress((void**)&xr,   g_xr);
    cudaGetSymbolAddress((void**)&h,    g_h);
    cudaGetSymbolAddress((void**)&degp, g_deg);

    cudaMemsetAsync(degp, 0, NN * sizeof(int));
    cudaMemsetAsync(out,  0, GG * C2 * sizeof(float));

    countprep_kernel<<<CNT_BLK + 32, 256>>>(ei, Wl2, Wr2);
    scan_kernel<<<1, 1024>>>();
    filllin1_kernel<<<FILL_BLK + NN / 8, 256>>>(ei, x, Wl1, bl1, Wr1, br1, xl, xr);
    gat_kernel<C1, false><<<NN, 64>>>(xl, xr, att1, b1, ln1g, ln1b, batch, h);
    lin2_kernel<<<NN / 32, 512>>>(h, bl2, br2, xl, xr);
    gat_kernel<C2, true><<<NN, 64>>>(xl, xr, att2, b2, ln2g, ln2b, batch, out);

    div_kernel<<<1, 256>>>(batch, out);
}

// round 16
// speedup vs baseline: 1.1736x; 1.1736x over previous
#include <cuda_runtime.h>
#include <cuda_fp16.h>
#include <math.h>

// ---------------- problem constants ----------------
#define NN    20000
#define EE    400000
#define ET    (EE + NN)
#define GG    200
#define C1    64
#define C2    32

// ---------------- persistent scratch ----------------
__device__ __align__(16) __half   g_xl[NN * 256];   // fp16 message table
__device__ __align__(16) float    g_xr[NN * 256];   // fp32 query table
__device__ __align__(16) float    g_h [NN * 64];    // inter-layer activations
__device__ __align__(16) __half2  g_w2h[32 * 256];  // packed layer-2 weights
__device__ __align__(16) int      g_deg[NN];        // zero-init; re-zeroed by div_kernel
__device__ __align__(16) int      g_pos[EE];
__device__ __align__(16) int      g_rowptr[NN + 4];
__device__ int                    g_csr[ET];

// ---------------- kernel 1: count + w2 pack + out zero ----------------
#define CNT_BLK 391                       // ceil(EE/4/256)
__global__ void countprep_kernel(const int* __restrict__ ei,
                                 const float* __restrict__ Wl2,
                                 const float* __restrict__ Wr2,
                                 float* __restrict__ outz) {
    if (blockIdx.x < CNT_BLK) {
        int i = blockIdx.x * blockDim.x + threadIdx.x;
        if (i >= EE / 4) return;
        int4 d = reinterpret_cast<const int4*>(ei + EE)[i];
        int4 p;
        p.x = atomicAdd(&g_deg[d.x], 1);
        p.y = atomicAdd(&g_deg[d.y], 1);
        p.z = atomicAdd(&g_deg[d.z], 1);
        p.w = atomicAdd(&g_deg[d.w], 1);
        reinterpret_cast<int4*>(g_pos)[i] = p;
    } else if (blockIdx.x < CNT_BLK + 32) {
        int i = (blockIdx.x - CNT_BLK) * blockDim.x + threadIdx.x;
        if (i >= 32 * 256) return;
        int kp = i >> 8, c = i & 255;
        float a, b;
        if (c < 128) { a = Wl2[(2 * kp) * 128 + c];       b = Wl2[(2 * kp + 1) * 128 + c]; }
        else         { a = Wr2[(2 * kp) * 128 + c - 128]; b = Wr2[(2 * kp + 1) * 128 + c - 128]; }
        g_w2h[i] = __floats2half2_rn(a, b);
    } else {
        // zero the pooled-output buffer (GG*C2 = 6400 floats)
        for (int i = threadIdx.x; i < GG * C2; i += blockDim.x)
            outz[i] = 0.f;
    }
}

// ---------------- kernel 2: scan ----------------
__global__ void scan_kernel() {
    __shared__ int sbuf[1024];
    int t = threadIdx.x;
    int4 v[5];
    int s = 0;
    const int4* d4 = reinterpret_cast<const int4*>(g_deg);
    if (t < 1000) {
#pragma unroll
        for (int i = 0; i < 5; i++) {
            v[i] = d4[t * 5 + i];
            s += v[i].x + v[i].y + v[i].z + v[i].w + 4;
        }
    }
    sbuf[t] = s;
    __syncthreads();
#pragma unroll
    for (int off = 1; off < 1024; off <<= 1) {
        int vv = (t >= off) ? sbuf[t - off] : 0;
        __syncthreads();
        sbuf[t] += vv;
        __syncthreads();
    }
    if (t < 1000) {
        int run = sbuf[t] - s;
        int4* rp4 = reinterpret_cast<int4*>(g_rowptr);
#pragma unroll
        for (int i = 0; i < 5; i++) {
            int4 o;
            o.x = run; run += v[i].x + 1;
            o.y = run; run += v[i].y + 1;
            o.z = run; run += v[i].z + 1;
            o.w = run; run += v[i].w + 1;
            rp4[t * 5 + i] = o;
        }
    }
    if (t == 1023) g_rowptr[NN] = sbuf[1023];
}

// ---------------- kernel 3: fill (1 edge/thread) fused with lin1 -------
#define FILL_BLK 1641                     // ceil(ET/256)
__global__ void __launch_bounds__(256, 6)
filllin1_kernel(const int* __restrict__ ei,
                const float* __restrict__ x,
                const float* __restrict__ Wl, const float* __restrict__ bl,
                const float* __restrict__ Wr, const float* __restrict__ br,
                __half* __restrict__ xl, float* __restrict__ xr) {
    if (blockIdx.x < FILL_BLK) {
        int i = blockIdx.x * blockDim.x + threadIdx.x;
        if (i >= ET) return;
        if (i < EE) {
            int src = ei[i];
            int dst = ei[EE + i];
            int pos = g_pos[i];
            g_csr[g_rowptr[dst] + pos] = src;
        } else {
            int n = i - EE;                // self loop -> last slot of row
            g_csr[g_rowptr[n] + g_deg[n]] = n;
        }
        return;
    }
    // ---- lin1: 8 rows per block, 256 threads ----
    __shared__ float xs[8 * 8];
    int n0 = (blockIdx.x - FILL_BLK) * 8;
    int tid = threadIdx.x;
    if (tid < 16)
        reinterpret_cast<float4*>(xs)[tid] =
            reinterpret_cast<const float4*>(x + n0 * 8)[tid];
    __syncthreads();

    int co = tid & 127;
    int r0 = (tid >> 7) * 4;
    int col = co * 4;
    bool left = (col < 256);
    const float* W    = left ? (Wl + col) : (Wr + col - 256);
    const float* bptr = left ? (bl + col) : (br + col - 256);
    float4 bv = *reinterpret_cast<const float4*>(bptr);
    float4 acc[4];
#pragma unroll
    for (int i = 0; i < 4; i++) acc[i] = bv;

#pragma unroll
    for (int k = 0; k < 8; k++) {
        float4 w = *reinterpret_cast<const float4*>(W + k * 256);
#pragma unroll
        for (int i = 0; i < 4; i++) {
            float xv = xs[(r0 + i) * 8 + k];
            acc[i].x += xv * w.x;
            acc[i].y += xv * w.y;
            acc[i].z += xv * w.z;
            acc[i].w += xv * w.w;
        }
    }
    if (left) {
#pragma unroll
        for (int i = 0; i < 4; i++) {
            __half2* p = reinterpret_cast<__half2*>(xl + (n0 + r0 + i) * 256 + col);
            p[0] = __floats2half2_rn(acc[i].x, acc[i].y);
            p[1] = __floats2half2_rn(acc[i].z, acc[i].w);
        }
    } else {
        int oc = col - 256;
#pragma unroll
        for (int i = 0; i < 4; i++)
            *reinterpret_cast<float4*>(xr + (n0 + r0 + i) * 256 + oc) = acc[i];
    }
}

// ---------------- kernel 4: GATv2 (1 warp per block = 1 node) ----------
template <int C, bool FINAL>
__global__ void gat_kernel(const __half* __restrict__ xl, const float* __restrict__ xr,
                           const float* __restrict__ att, const float* __restrict__ bias,
                           const float* __restrict__ lng, const float* __restrict__ lnb,
                           const int* __restrict__ batch, float* __restrict__ outp) {
    constexpr int D   = 4 * C;
    constexpr int VPL = C / 8;
    constexpr int H2  = VPL / 2;
    int gw = blockIdx.x;
    int lane = threadIdx.x;
    int h  = lane >> 3;
    int cl = lane & 7;

    __half2 a2[H2], q2[H2];
    const float* attp = att + h * C + cl * VPL;
    const float* qp   = xr + gw * D + lane * VPL;
#pragma unroll
    for (int i = 0; i < H2; i++) {
        a2[i] = __floats2half2_rn(attp[2 * i] * 1.44269504f,
                                  attp[2 * i + 1] * 1.44269504f);
        q2[i] = __floats2half2_rn(qp[2 * i], qp[2 * i + 1]);
    }
    float acc[VPL];
#pragma unroll
    for (int i = 0; i < VPL; i++) acc[i] = 0.f;
    float s = 0.f;

    const __half2 c02 = __floats2half2_rn(0.2f, 0.2f);
    const __half* rowp = xl + lane * VPL;

    auto loadv = [&](__half2* hv, int src) {
        if (C == 64)
            *reinterpret_cast<uint4*>(hv) = *reinterpret_cast<const uint4*>(rowp + src * D);
        else
            *reinterpret_cast<uint2*>(hv) = *reinterpret_cast<const uint2*>(rowp + src * D);
    };
    auto score = [&](__half2* hv) -> __half2 {
        __half2 p2 = __floats2half2_rn(0.f, 0.f);
#pragma unroll
        for (int i = 0; i < H2; i++) {
            __half2 v  = __hadd2(hv[i], q2[i]);
            __half2 lr = __hmax2(v, __hmul2(v, c02));
            p2 = __hfma2(a2[i], lr, p2);
        }
        return p2;
    };

    int kb = g_rowptr[gw], ke = g_rowptr[gw + 1];
    int k = kb;
    int i0, i1, i2, i3;
    if (k + 4 <= ke) {
        i0 = g_csr[k]; i1 = g_csr[k + 1]; i2 = g_csr[k + 2]; i3 = g_csr[k + 3];
    }
    while (k + 4 <= ke) {
        __half2 hv0[H2], hv1[H2], hv2[H2], hv3[H2];
        loadv(hv0, i0); loadv(hv1, i1); loadv(hv2, i2); loadv(hv3, i3);
        k += 4;
        if (k + 4 <= ke) {   // prefetch next group's indices
            i0 = g_csr[k]; i1 = g_csr[k + 1]; i2 = g_csr[k + 2]; i3 = g_csr[k + 3];
        }
        __half2 p0 = score(hv0), p1 = score(hv1), p2 = score(hv2), p3 = score(hv3);
        // pair edges: r01 = {sum(p0), sum(p1)}, r23 = {sum(p2), sum(p3)}
        __half2 r01 = __hadd2(__lows2half2(p0, p1), __highs2half2(p0, p1));
        __half2 r23 = __hadd2(__lows2half2(p2, p3), __highs2half2(p2, p3));
#pragma unroll
        for (int off = 1; off < 8; off <<= 1) {
            unsigned u01 = __shfl_xor_sync(0xffffffffu,
                           *reinterpret_cast<unsigned*>(&r01), off);
            unsigned u23 = __shfl_xor_sync(0xffffffffu,
                           *reinterpret_cast<unsigned*>(&r23), off);
            r01 = __hadd2(r01, *reinterpret_cast<__half2*>(&u01));
            r23 = __hadd2(r23, *reinterpret_cast<__half2*>(&u23));
        }
        float2 f01 = __half22float2(r01);
        float2 f23 = __half22float2(r23);
        float al0 = exp2f(f01.x);
        float al1 = exp2f(f01.y);
        float al2 = exp2f(f23.x);
        float al3 = exp2f(f23.y);
        s += (al0 + al1) + (al2 + al3);
        // half2 2-term partial chains, flushed to fp32 once per group
        __half2 al0h = __float2half2_rn(al0);
        __half2 al1h = __float2half2_rn(al1);
        __half2 al2h = __float2half2_rn(al2);
        __half2 al3h = __float2half2_rn(al3);
#pragma unroll
        for (int i = 0; i < H2; i++) {
            __half2 t = __hmul2(al0h, hv0[i]);
            t = __hfma2(al1h, hv1[i], t);
            __half2 u = __hmul2(al2h, hv2[i]);
            u = __hfma2(al3h, hv3[i], u);
            float2 ft = __half22float2(t);
            float2 fu = __half22float2(u);
            acc[2 * i]     += ft.x + fu.x;
            acc[2 * i + 1] += ft.y + fu.y;
        }
    }
    for (; k < ke; k++) {
        __half2 hv[H2];
        loadv(hv, g_csr[k]);
        __half2 p2 = score(hv);
#pragma unroll
        for (int off = 1; off < 8; off <<= 1) {
            unsigned pu = __shfl_xor_sync(0xffffffffu,
                          *reinterpret_cast<unsigned*>(&p2), off);
            p2 = __hadd2(p2, *reinterpret_cast<__half2*>(&pu));
        }
        float2 pf = __half22float2(p2);
        float al = exp2f(pf.x + pf.y);
        s += al;
#pragma unroll
        for (int i = 0; i < H2; i++) {
            float2 f = __half22float2(hv[i]);
            acc[2 * i]     += al * f.x;
            acc[2 * i + 1] += al * f.y;
        }
    }

    float inv = 1.f / s;
#pragma unroll
    for (int i = 0; i < VPL; i++) acc[i] *= inv;
#pragma unroll
    for (int i = 0; i < VPL; i++) {
        acc[i] += __shfl_xor_sync(0xffffffffu, acc[i], 8);
        acc[i] += __shfl_xor_sync(0xffffffffu, acc[i], 16);
    }
    float u[VPL];
    const float* bp = bias + cl * VPL;
    float tot = 0.f;
#pragma unroll
    for (int i = 0; i < VPL; i++) { u[i] = acc[i] * 0.25f + bp[i]; tot += u[i]; }
#pragma unroll
    for (int off = 16; off >= 1; off >>= 1)
        tot += __shfl_xor_sync(0xffffffffu, tot, off);
    float mean = tot * (1.f / (4.f * C));
    float d[VPL], var = 0.f;
#pragma unroll
    for (int i = 0; i < VPL; i++) { d[i] = u[i] - mean; var += d[i] * d[i]; }
#pragma unroll
    for (int off = 16; off >= 1; off >>= 1)
        var += __shfl_xor_sync(0xffffffffu, var, off);
    float rstd = rsqrtf(var * (1.f / (4.f * C)) + 1e-5f);

    const float* gp = lng + cl * VPL;
    const float* b2 = lnb + cl * VPL;
    float y[VPL];
#pragma unroll
    for (int i = 0; i < VPL; i++)
        y[i] = fmaxf(d[i] * rstd * gp[i] + b2[i], 0.f);

    if (lane < 8) {
        if (FINAL) {
            int bg = batch[gw];
#pragma unroll
            for (int i = 0; i < VPL; i++)
                atomicAdd(&outp[bg * C + cl * VPL + i], y[i]);
        } else {
            float* op = outp + gw * C + cl * VPL;
            *reinterpret_cast<float4*>(op) = make_float4(y[0], y[1], y[2], y[3]);
            if (VPL == 8)
                *reinterpret_cast<float4*>(op + 4) = make_float4(y[4], y[5], y[6], y[7]);
        }
    }
}

// ---------------- kernel 5: layer-2 linear (half2 split-K) ----------------
__global__ void __launch_bounds__(512, 2)
lin2_kernel(const float* __restrict__ xin,
            const float* __restrict__ bl, const float* __restrict__ br,
            __half* __restrict__ xl, float* __restrict__ xr) {
    __shared__ __half2 xs2[32 * 32];
    int n0 = blockIdx.x * 32;
    int tid = threadIdx.x;
    for (int idx = tid; idx < 32 * 32; idx += 512) {
        int row = idx >> 5, kp = idx & 31;
        float2 v = *reinterpret_cast<const float2*>(xin + (n0 + row) * 64 + 2 * kp);
        xs2[idx] = __floats2half2_rn(v.x, v.y);
    }
    __syncthreads();

    int co = tid & 63;
    int r0 = (tid >> 6) * 4;
    int col = co * 4;
    bool left = (col < 128);
    const float* bptr = left ? (bl + col) : (br + col - 128);
    float4 bv = *reinterpret_cast<const float4*>(bptr);
    float4 accf[4];
#pragma unroll
    for (int i = 0; i < 4; i++) accf[i] = bv;

    const __half2* wp = g_w2h + co * 4;
#pragma unroll
    for (int ch = 0; ch < 2; ch++) {
        __half2 ah[4][4];
#pragma unroll
        for (int r = 0; r < 4; r++)
#pragma unroll
            for (int c = 0; c < 4; c++) ah[r][c] = __floats2half2_rn(0.f, 0.f);
#pragma unroll
        for (int kp = 0; kp < 16; kp++) {
            int kk = ch * 16 + kp;
            uint4 wv = *reinterpret_cast<const uint4*>(wp + kk * 256);
            __half2 w0 = *reinterpret_cast<__half2*>(&wv.x);
            __half2 w1 = *reinterpret_cast<__half2*>(&wv.y);
            __half2 w2 = *reinterpret_cast<__half2*>(&wv.z);
            __half2 w3 = *reinterpret_cast<__half2*>(&wv.w);
#pragma unroll
            for (int r = 0; r < 4; r++) {
                __half2 xp = xs2[(r0 + r) * 32 + kk];
                ah[r][0] = __hfma2(xp, w0, ah[r][0]);
                ah[r][1] = __hfma2(xp, w1, ah[r][1]);
                ah[r][2] = __hfma2(xp, w2, ah[r][2]);
                ah[r][3] = __hfma2(xp, w3, ah[r][3]);
            }
        }
#pragma unroll
        for (int r = 0; r < 4; r++) {
            float2 f;
            f = __half22float2(ah[r][0]); accf[r].x += f.x + f.y;
            f = __half22float2(ah[r][1]); accf[r].y += f.x + f.y;
            f = __half22float2(ah[r][2]); accf[r].z += f.x + f.y;
            f = __half22float2(ah[r][3]); accf[r].w += f.x + f.y;
        }
    }

    if (left) {
#pragma unroll
        for (int i = 0; i < 4; i++) {
            __half2* p = reinterpret_cast<__half2*>(xl + (n0 + r0 + i) * 128 + col);
            p[0] = __floats2half2_rn(accf[i].x, accf[i].y);
            p[1] = __floats2half2_rn(accf[i].z, accf[i].w);
        }
    } else {
        int oc = col - 128;
#pragma unroll
        for (int i = 0; i < 4; i++)
            *reinterpret_cast<float4*>(xr + (n0 + r0 + i) * 128 + oc) = accf[i];
    }
}

// ---------------- kernel 6: divide pooled sums + re-zero g_deg ---------
__global__ void div_kernel(const int* __restrict__ batch, float* __restrict__ out) {
    // all blocks: grid-stride clear of g_deg for the NEXT replay
    int gi = blockIdx.x * blockDim.x + threadIdx.x;
    if (gi < NN) g_deg[gi] = 0;

    if (blockIdx.x != 0) return;
    int t = threadIdx.x;
    if (t >= GG) return;
    int lo0 = 0, hi0 = NN;
    while (lo0 < hi0) { int mid = (lo0 + hi0) >> 1; if (batch[mid] < t) lo0 = mid + 1; else hi0 = mid; }
    int lo1 = lo0, hi1 = NN;
    while (lo1 < hi1) { int mid = (lo1 + hi1) >> 1; if (batch[mid] < t + 1) lo1 = mid + 1; else hi1 = mid; }
    float invc = 1.f / fmaxf((float)(lo1 - lo0), 1.f);
    float4* o4 = reinterpret_cast<float4*>(out + t * C2);
#pragma unroll
    for (int i = 0; i < C2 / 4; i++) {
        float4 v = o4[i];
        v.x *= invc; v.y *= invc; v.z *= invc; v.w *= invc;
        o4[i] = v;
    }
}

// ---------------- launch ----------------
extern "C" void kernel_launch(void* const* d_in, const int* in_sizes, int n_in,
                              void* d_out, int out_size) {
    const float* x     = (const float*)d_in[0];
    const int*   ei    = (const int*)  d_in[1];
    const int*   batch = (const int*)  d_in[2];
    const float* Wl1   = (const float*)d_in[3];
    const float* bl1   = (const float*)d_in[4];
    const float* Wr1   = (const float*)d_in[5];
    const float* br1   = (const float*)d_in[6];
    const float* att1  = (const float*)d_in[7];
    const float* b1    = (const float*)d_in[8];
    const float* ln1g  = (const float*)d_in[9];
    const float* ln1b  = (const float*)d_in[10];
    const float* Wl2   = (const float*)d_in[11];
    const float* bl2   = (const float*)d_in[12];
    const float* Wr2   = (const float*)d_in[13];
    const float* br2   = (const float*)d_in[14];
    const float* att2  = (const float*)d_in[15];
    const float* b2    = (const float*)d_in[16];
    const float* ln2g  = (const float*)d_in[17];
    const float* ln2b  = (const float*)d_in[18];
    float* out = (float*)d_out;

    __half* xl; float *xr, *h;
    cudaGetSymbolAddress((void**)&xl, g_xl);
    cudaGetSymbolAddress((void**)&xr, g_xr);
    cudaGetSymbolAddress((void**)&h,  g_h);

    countprep_kernel<<<CNT_BLK + 33, 256>>>(ei, Wl2, Wr2, out);
    scan_kernel<<<1, 1024>>>();
    filllin1_kernel<<<FILL_BLK + NN / 8, 256>>>(ei, x, Wl1, bl1, Wr1, br1, xl, xr);
    gat_kernel<C1, false><<<NN, 32>>>(xl, xr, att1, b1, ln1g, ln1b, batch, h);
    lin2_kernel<<<NN / 32, 512>>>(h, bl2, br2, xl, xr);
    gat_kernel<C2, true><<<NN, 32>>>(xl, xr, att2, b2, ln2g, ln2b, batch, out);

    div_kernel<<<(NN + 255) / 256, 256>>>(batch, out);
}